// round 11
// baseline (speedup 1.0000x reference)
#include <cuda_runtime.h>
#include <cstdint>

// ---------------------------------------------------------------------------
// SSDTargetGenerator for GB300.  (R11: SOLVED layout — reference box_masks is
// shape (1,N,1) (pos[:,None] broadcast against scalars), so the output buffer
// is [cls(N) | box(4N) | mask(N)] = 6N elements, mask scalar at 5N+i.
// This explains R1's OOB crash (9N write), R9's box=1.0 (has_box 9N guard),
// and R10's mask rel_err 1.358 ((N,4)-interleaved mask vs (N,1) reference).)
// Pipeline: [k_zero tail-only] -> k_iou -> k_select -> k_greedy -> k_out
// All scratch is __device__ global (no allocation). All launches graph-capturable.
// ---------------------------------------------------------------------------

#define MAXM  128      // max gt boxes supported
#define TOPK  128      // per-column candidate list (> M so M-1 removals can't drain it)
#define CAP   65536    // per-column raw candidate capacity (expected ~8K, worst ~26K)
#define MAXN  131072   // max anchors supported (N=120000)

__device__ float g_cand_iou[MAXM][CAP];
__device__ int   g_cand_cnt[MAXM];          // zero-init at load; re-zeroed by k_greedy
__device__ int   g_cand_row[MAXM][CAP];
__device__ float g_top_iou[MAXM][TOPK];
__device__ int   g_top_row[MAXM][TOPK];
__device__ int   g_top_cnt[MAXM];
__device__ int   g_match[MAXN];

// ---------------------------------------------------------------- k_zero ----
// Only launched when out_size > 6N: zeroes the tail k_out won't cover.
__global__ void k_zero(float* __restrict__ out, int zero_from, int out_size) {
    int stride = gridDim.x * blockDim.x;
    for (int i = zero_from + blockIdx.x * blockDim.x + threadIdx.x;
         i < out_size; i += stride)
        out[i] = 0.0f;
}

// ----------------------------------------------------------------- k_iou ----
// Per anchor: IoU vs all M gt boxes. Per-anchor argmax (first-occurrence
// tie-break == jnp.argmax) for MaximumMatcher; appends iou > 1e-12 candidates
// to per-column buffers via warp-aggregated atomics (c-loop is warp-uniform).
__global__ void k_iou(const float4* __restrict__ anchors,
                      const float4* __restrict__ gt,
                      int N, int M) {
    __shared__ float4 s_gt[MAXM];
    __shared__ float  s_area[MAXM];
    for (int c = threadIdx.x; c < M; c += blockDim.x) {
        float4 g = gt[c];
        s_gt[c] = g;
        s_area[c] = (g.z - g.x) * (g.w - g.y);
    }
    __syncthreads();

    const int i = blockIdx.x * blockDim.x + threadIdx.x;
    const bool active = (i < N && i < MAXN);
    const unsigned lane = threadIdx.x & 31u;

    float4 a = make_float4(0.f, 0.f, 0.f, 0.f);
    if (active) a = anchors[i];                // center format (cx,cy,w,h)
    float hw = a.z * 0.5f, hh = a.w * 0.5f;
    float ax1 = a.x - hw, ay1 = a.y - hh;
    float ax2 = a.x + hw, ay2 = a.y + hh;
    float area_a = (ax2 - ax1) * (ay2 - ay1);  // replicate reference op order

    float best = 0.0f;
    int   argc = 0;

    for (int c = 0; c < M; ++c) {
        float4 g = s_gt[c];
        float tlx = fmaxf(ax1, g.x), tly = fmaxf(ay1, g.y);
        float brx = fminf(ax2, g.z), bry = fminf(ay2, g.w);
        float wx = brx - tlx, wy = bry - tly;

        float iou = 0.0f;
        bool cand = false;
        if (active && wx > 0.0f && wy > 0.0f) {
            float inter = wx * wy;
            iou = inter / (area_a + s_area[c] - inter);     // IEEE div, matches ref
            if (iou > best) { best = iou; argc = c; }       // first-occurrence argmax
            cand = (iou > 1e-12f);
        }

        unsigned mask = __ballot_sync(0xFFFFFFFFu, cand);
        if (mask) {
            int cnt  = __popc(mask);
            int base = 0;
            int leader = __ffs(mask) - 1;
            if ((int)lane == leader) base = atomicAdd(&g_cand_cnt[c], cnt);
            base = __shfl_sync(0xFFFFFFFFu, base, leader);
            if (cand) {
                int idx = base + __popc(mask & ((1u << lane) - 1u));
                if (idx < CAP) {
                    g_cand_iou[c][idx] = iou;
                    g_cand_row[c][idx] = i;
                }
            }
        }
    }
    if (active) g_match[i] = (best >= 0.5f) ? argc : -1;    // MaximumMatcher
}

// -------------------------------------------------------------- k_select ----
// Per column: exact K-th-largest radix-select over candidate IoUs (positive
// floats <= 1.0 -> uint order == float order, bit 30 == 0), gather top-K,
// rank-sort desc by iou with row-ascending tie-break (argmax order).
__global__ void k_select() {
    const int c   = blockIdx.x;
    const int tid = threadIdx.x;
    int n = g_cand_cnt[c]; if (n > CAP) n = CAP;
    const int K = n < TOPK ? n : TOPK;
    if (K == 0) { if (tid == 0) g_top_cnt[c] = 0; return; }

    const float* __restrict__ iou  = g_cand_iou[c];
    const int*   __restrict__ rows = g_cand_row[c];

    __shared__ int   s_red[256];
    __shared__ int   s_pos;
    __shared__ int   s_eqn;
    __shared__ int   s_eqrows[256];
    __shared__ float s_v[TOPK];
    __shared__ int   s_r[TOPK];

    unsigned prefix = 0u;
    for (int b = 29; b >= 0; --b) {
        unsigned test = prefix | (1u << b);
        int local = 0;
        for (int i = tid; i < n; i += blockDim.x)
            local += (__float_as_uint(iou[i]) >= test) ? 1 : 0;
        s_red[tid] = local;
        __syncthreads();
        for (int s = 128; s > 0; s >>= 1) {
            if (tid < s) s_red[tid] += s_red[tid + s];
            __syncthreads();
        }
        int total = s_red[0];
        __syncthreads();
        if (total >= K) prefix = test;
    }
    const unsigned T = prefix;

    if (tid == 0) s_pos = 0;
    __syncthreads();
    for (int i = tid; i < n; i += blockDim.x) {
        if (__float_as_uint(iou[i]) > T) {
            int p = atomicAdd(&s_pos, 1);
            if (p < TOPK) {
                g_top_iou[c][p] = iou[i];
                g_top_row[c][p] = rows[i];
            }
        }
    }
    __syncthreads();
    const int cnt_gt = s_pos < TOPK ? s_pos : TOPK;
    const int need   = K - cnt_gt;   // >= 1 by construction of T

    if (tid == 0) s_eqn = 0;
    __syncthreads();
    for (int i = tid; i < n; i += blockDim.x) {
        if (__float_as_uint(iou[i]) == T) {
            int p = atomicAdd(&s_eqn, 1);
            if (p < 256) s_eqrows[p] = rows[i];
        }
    }
    __syncthreads();
    const int eqn = s_eqn < 256 ? s_eqn : 256;
    if (tid < eqn) {
        int r = s_eqrows[tid];
        int rank = 0;
        for (int j = 0; j < eqn; ++j) rank += (s_eqrows[j] < r) ? 1 : 0;
        if (rank < need && (cnt_gt + rank) < TOPK) {
            g_top_iou[c][cnt_gt + rank] = __uint_as_float(T);
            g_top_row[c][cnt_gt + rank] = r;
        }
    }
    __syncthreads();

    if (tid < K) { s_v[tid] = g_top_iou[c][tid]; s_r[tid] = g_top_row[c][tid]; }
    __syncthreads();
    if (tid < K) {
        float v = s_v[tid]; int r = s_r[tid];
        int rank = 0;
        for (int j = 0; j < K; ++j) {
            float vj = s_v[j]; int rj = s_r[j];
            rank += ((vj > v) || (vj == v && rj < r)) ? 1 : 0;
        }
        if (rank < TOPK) {
            g_top_iou[c][rank] = v;
            g_top_row[c][rank] = r;
        }
    }
    if (tid == 0) g_top_cnt[c] = K;
}

// -------------------------------------------------------------- k_greedy ----
// Single block, M iterations: per-column best unremoved candidate, global max
// with flattened-index tie-break (r*M + c == jnp.argmax), mask row+col.
// Re-zeros g_cand_cnt at exit (entry invariant for graph replays).
__global__ void k_greedy(int N, int M) {
    __shared__ unsigned s_removed[MAXN / 32];
    __shared__ float s_cv[128];
    __shared__ int   s_cr[128];
    __shared__ unsigned char s_matched[128];
    __shared__ int s_bestc, s_bestr;

    const int tid = threadIdx.x;                // blockDim = 128
    for (int i = tid; i < MAXN / 32; i += 128) s_removed[i] = 0;
    s_matched[tid] = 0;

    int ptr = 0;
    const int cnt = (tid < M) ? g_top_cnt[tid] : 0;
    __syncthreads();

    for (int it = 0; it < M; ++it) {
        float v = -1.0f; int r = 0;
        if (tid < M && !s_matched[tid]) {
            while (ptr < cnt) {
                int row = g_top_row[tid][ptr];
                if (s_removed[row >> 5] & (1u << (row & 31))) { ++ptr; continue; }
                v = g_top_iou[tid][ptr];
                r = row;
                break;
            }
        }
        s_cv[tid] = v; s_cr[tid] = r;
        __syncthreads();

        if (tid == 0) {
            float bv = -1.0f; int bc = -1, br = 0;
            for (int c2 = 0; c2 < M; ++c2) {
                float vv = s_cv[c2];
                if (vv < 0.0f) continue;
                int rr = s_cr[c2];
                bool better;
                if (bc < 0) better = true;
                else better = (vv > bv) ||
                              (vv == bv && ((long long)rr * M + c2) < ((long long)br * M + bc));
                if (better) { bv = vv; bc = c2; br = rr; }
            }
            s_bestc = bc; s_bestr = br;
            if (bc >= 0) {
                s_matched[bc] = 1;
                s_removed[br >> 5] |= 1u << (br & 31);
                if (br < MAXN) g_match[br] = bc;
            }
        }
        __syncthreads();
        if (s_bestc < 0) break;
        __syncthreads();
    }

    if (tid < MAXM) g_cand_cnt[tid] = 0;
}

// ----------------------------------------------------------------- k_out ----
// Per anchor, layout [cls(N) | box(4N) | mask(N)] = 6N elements:
//   cls  at out[i]
//   box  at out[N + 4*i .. +3]    (shape (1,N,4))
//   mask at out[5N + i]           (shape (1,N,1) — pos[:,None] broadcast!)
// Stores still guarded by out_size (belt and braces).
__global__ void k_out(const float4* __restrict__ anchors,
                      const float4* __restrict__ gt,
                      const int* __restrict__ gt_ids,
                      int N, int M, float* __restrict__ out, int out_size) {
    int i = blockIdx.x * blockDim.x + threadIdx.x;
    if (i >= N || i >= MAXN) return;

    int m = g_match[i];
    if (m >= M) m = -1;                          // defensive clamp
    const bool pos = (m >= 0);

    float cls_v = 0.0f;
    float t0 = 0.0f, t1 = 0.0f, t2 = 0.0f, t3 = 0.0f, mk = 0.0f;

    if (pos) {
        cls_v = (float)gt_ids[m] + 1.0f;
        mk = 1.0f;

        float4 g = gt[m];                        // corner format
        float gw = g.z - g.x, gh = g.w - g.y;
        float gcx = g.x + 0.5f * gw, gcy = g.y + 0.5f * gh;

        float4 a = anchors[i];                   // center format
        float hw = a.z * 0.5f, hh = a.w * 0.5f;
        float ax1 = a.x - hw, ay1 = a.y - hh;
        float ax2 = a.x + hw, ay2 = a.y + hh;
        float aw = ax2 - ax1, ah = ay2 - ay1;
        float acx = ax1 + 0.5f * aw, acy = ay1 + 0.5f * ah;

        t0 = (gcx - acx) / aw / 0.1f;
        t1 = (gcy - acy) / ah / 0.1f;
        t2 = logf(gw / aw) / 0.2f;
        t3 = logf(gh / ah) / 0.2f;
    }

    // cls at [0, N)
    if (i < out_size) out[i] = cls_v;

    // box targets at [N, 5N), (N,4) row-major
    {
        int b0 = N + 4 * i;
        if (b0 + 3 < out_size) {
            *(float4*)(out + b0) = make_float4(t0, t1, t2, t3);
        } else {
            if (b0 + 0 < out_size) out[b0 + 0] = t0;
            if (b0 + 1 < out_size) out[b0 + 1] = t1;
            if (b0 + 2 < out_size) out[b0 + 2] = t2;
            if (b0 + 3 < out_size) out[b0 + 3] = t3;
        }
    }

    // box mask at [5N, 6N), ONE scalar per anchor
    {
        int m0 = 5 * N + i;
        if (m0 < out_size) out[m0] = mk;
    }
}

// ---------------------------------------------------------------------------
extern "C" void kernel_launch(void* const* d_in, const int* in_sizes, int n_in,
                              void* d_out, int out_size) {
    const float4* anchors = (const float4*)d_in[0];   // (N,4) center format
    const float4* gt      = (const float4*)d_in[1];   // (M,4) corner format
    const int*    gt_ids  = (const int*)d_in[2];      // (M,1) int32

    int N = in_sizes[0] / 4;
    int M = in_sizes[1] / 4;
    if (N > MAXN) N = MAXN;                           // defensive clamps
    if (M > MAXM) M = MAXM;
    float* out = (float*)d_out;

    // k_out covers [0, min(6N, out_size)); zero any tail beyond 6N.
    if (out_size > 6 * N) {
        int tail = out_size - 6 * N;
        int zgrid = (tail + 255) / 256;
        if (zgrid > 1184) zgrid = 1184;
        k_zero<<<zgrid, 256>>>(out, 6 * N, out_size);
    }

    k_iou<<<(N + 255) / 256, 256>>>(anchors, gt, N, M);
    k_select<<<M, 256>>>();
    k_greedy<<<1, 128>>>(N, M);
    k_out<<<(N + 255) / 256, 256>>>(anchors, gt, gt_ids, N, M, out, out_size);
}

// round 13
// speedup vs baseline: 2.3424x; 2.3424x over previous
#include <cuda_runtime.h>
#include <cstdint>

// ---------------------------------------------------------------------------
// SSDTargetGenerator for GB300.  R13 = resubmit of unbenched R12 (broker
// timeout). R11 passed (rel_err 4.4e-8) at 600.9us; k_out measured 6.3us, so
// ~594us was k_iou's dependent same-address ATOMG round-trips (~333K
// serialized atomics on 100 counters). Design:
//   k_iou    : dense column-major IoU matrix (coalesced stores, no atomics)
//   k_select : per-column block; warp-segmented compaction (ballot+popc only),
//              zero-filled tails, then the VALIDATED radix top-128 + rank-sort
//   k_greedy : packed-u64 shared atomicMax argmax (iou desc, flat idx asc)
//   k_out    : unchanged (layout [cls(N)|box(4N)|mask(N)], bit-exact)
// No global atomics anywhere. No cross-launch state. Graph-capturable.
// ---------------------------------------------------------------------------

#define MAXM    128     // max gt boxes
#define TOPK    128     // per-column survivor list (> M-1 removals)
#define MAXN    131072  // max anchors (N=120000)
#define SEGS    8       // warps per k_select block
#define SEGCAP  2048    // per-warp segment capacity (expected ~990, 35 sigma)

__device__ float g_iou_mat[(size_t)MAXM * MAXN];   // column-major [c*N + i]
__device__ float g_cv[MAXM][SEGS * SEGCAP];        // per-column compacted vals
__device__ int   g_cr[MAXM][SEGS * SEGCAP];        // per-column compacted rows
__device__ float g_top_iou[MAXM][TOPK];
__device__ int   g_top_row[MAXM][TOPK];
__device__ int   g_top_cnt[MAXM];
__device__ int   g_match[MAXN];

// ---------------------------------------------------------------- k_zero ----
// Only if out_size > 6N: zero the tail k_out won't cover.
__global__ void k_zero(float* __restrict__ out, int zero_from, int out_size) {
    int stride = gridDim.x * blockDim.x;
    for (int i = zero_from + blockIdx.x * blockDim.x + threadIdx.x;
         i < out_size; i += stride)
        out[i] = 0.0f;
}

// ----------------------------------------------------------------- k_iou ----
// Per anchor: IoU vs all M gt boxes. Per-anchor argmax (first-occurrence
// tie-break == jnp.argmax) for MaximumMatcher. Dense matrix store: value if
// iou > 1e-12 (bipartite threshold) else 0. At column c, thread i stores
// mat[c*N+i] -> fully coalesced. No atomics, no ballots.
__global__ void k_iou(const float4* __restrict__ anchors,
                      const float4* __restrict__ gt,
                      int N, int M) {
    __shared__ float4 s_gt[MAXM];
    __shared__ float  s_area[MAXM];
    for (int c = threadIdx.x; c < M; c += blockDim.x) {
        float4 g = gt[c];
        s_gt[c] = g;
        s_area[c] = (g.z - g.x) * (g.w - g.y);
    }
    __syncthreads();

    const int i = blockIdx.x * blockDim.x + threadIdx.x;
    if (i >= N || i >= MAXN) return;

    float4 a = anchors[i];                     // center format (cx,cy,w,h)
    float hw = a.z * 0.5f, hh = a.w * 0.5f;
    float ax1 = a.x - hw, ay1 = a.y - hh;
    float ax2 = a.x + hw, ay2 = a.y + hh;
    float area_a = (ax2 - ax1) * (ay2 - ay1);  // replicate reference op order

    float best = 0.0f;
    int   argc = 0;

    #pragma unroll 4
    for (int c = 0; c < M; ++c) {
        float4 g = s_gt[c];
        float tlx = fmaxf(ax1, g.x), tly = fmaxf(ay1, g.y);
        float brx = fminf(ax2, g.z), bry = fminf(ay2, g.w);
        float wx = brx - tlx, wy = bry - tly;

        float val = 0.0f;
        if (wx > 0.0f && wy > 0.0f) {
            float inter = wx * wy;
            float iou = inter / (area_a + s_area[c] - inter);   // IEEE div == ref
            if (iou > best) { best = iou; argc = c; }           // first-occurrence
            if (iou > 1e-12f) val = iou;
        }
        g_iou_mat[(size_t)c * N + i] = val;
    }
    g_match[i] = (best >= 0.5f) ? argc : -1;   // MaximumMatcher
}

// -------------------------------------------------------------- k_select ----
// One block (256 thr) per column. Phase 1: stream the contiguous column,
// compact positives into per-warp segments (ballot+popc, register offset —
// zero atomics), zero-fill tails. Phase 2: the validated exact radix
// top-128 (K-th largest threshold T; zeros can never pass since T>0),
// gather >T, ==T smallest rows, rank-sort (iou desc, row asc) — argmax order.
__global__ void k_select(int N, int M) {
    const int c    = blockIdx.x;
    const int tid  = threadIdx.x;
    const int wid  = tid >> 5;
    const int lane = tid & 31;

    const float* __restrict__ col = g_iou_mat + (size_t)c * N;
    float* __restrict__ cv = g_cv[c];
    int*   __restrict__ cr = g_cr[c];

    __shared__ int   s_cnt[SEGS];
    __shared__ int   s_red[256];
    __shared__ int   s_pos;
    __shared__ int   s_eqn;
    __shared__ int   s_eqrows[256];
    __shared__ float s_v[TOPK];
    __shared__ int   s_r[TOPK];

    // Phase 1: warp-segmented compaction (lanes of a warp read 32 contiguous)
    const int wbase = wid * SEGCAP;
    int woff = 0;                               // warp-uniform running offset
    for (int i = tid; i < N; i += 256) {
        float v = col[i];
        unsigned m = __ballot_sync(0xFFFFFFFFu, v > 0.0f);
        if (v > 0.0f) {
            int p = woff + __popc(m & ((1u << lane) - 1u));
            if (p < SEGCAP) { cv[wbase + p] = v; cr[wbase + p] = i; }
        }
        woff += __popc(m);
    }
    int wcnt = woff < SEGCAP ? woff : SEGCAP;
    if (lane == 0) s_cnt[wid] = wcnt;
    // zero-fill this warp's tail so radix can run over the fixed window
    for (int k = wcnt + lane; k < SEGCAP; k += 32) cv[wbase + k] = 0.0f;
    __syncthreads();

    int n_total = 0;
    #pragma unroll
    for (int w = 0; w < SEGS; ++w) n_total += s_cnt[w];

    const int K = n_total < TOPK ? n_total : TOPK;
    if (K == 0) { if (tid == 0) g_top_cnt[c] = 0; return; }

    const int n = SEGS * SEGCAP;               // fixed window, zeros padded

    // Radix binary search for T = K-th largest (IoU in (0,1] -> bit30 == 0;
    // zero slots have bits 0 and never satisfy >= test since test >= 1).
    unsigned prefix = 0u;
    for (int b = 29; b >= 0; --b) {
        unsigned test = prefix | (1u << b);
        int local = 0;
        for (int i = tid; i < n; i += 256)
            local += (__float_as_uint(cv[i]) >= test) ? 1 : 0;
        s_red[tid] = local;
        __syncthreads();
        for (int s = 128; s > 0; s >>= 1) {
            if (tid < s) s_red[tid] += s_red[tid + s];
            __syncthreads();
        }
        int total = s_red[0];
        __syncthreads();
        if (total >= K) prefix = test;
    }
    const unsigned T = prefix;                  // T > 0 since K <= n_total

    // Gather strictly-greater entries (unordered; sorted below)
    if (tid == 0) s_pos = 0;
    __syncthreads();
    for (int i = tid; i < n; i += 256) {
        if (__float_as_uint(cv[i]) > T) {
            int p = atomicAdd(&s_pos, 1);       // shared, < 128 total
            if (p < TOPK) {
                g_top_iou[c][p] = cv[i];
                g_top_row[c][p] = cr[i];
            }
        }
    }
    __syncthreads();
    const int cnt_gt = s_pos < TOPK ? s_pos : TOPK;
    const int need   = K - cnt_gt;              // >= 1 by construction of T

    // Entries equal to T: keep the 'need' smallest rows (argmax tie order)
    if (tid == 0) s_eqn = 0;
    __syncthreads();
    for (int i = tid; i < n; i += 256) {
        if (__float_as_uint(cv[i]) == T) {
            int p = atomicAdd(&s_eqn, 1);
            if (p < 256) s_eqrows[p] = cr[i];
        }
    }
    __syncthreads();
    const int eqn = s_eqn < 256 ? s_eqn : 256;
    if (tid < eqn) {
        int r = s_eqrows[tid];
        int rank = 0;
        for (int j = 0; j < eqn; ++j) rank += (s_eqrows[j] < r) ? 1 : 0;
        if (rank < need && (cnt_gt + rank) < TOPK) {
            g_top_iou[c][cnt_gt + rank] = __uint_as_float(T);
            g_top_row[c][cnt_gt + rank] = r;
        }
    }
    __syncthreads();

    // Rank-sort K entries: iou descending, row ascending on ties
    if (tid < K) { s_v[tid] = g_top_iou[c][tid]; s_r[tid] = g_top_row[c][tid]; }
    __syncthreads();
    if (tid < K) {
        float v = s_v[tid]; int r = s_r[tid];
        int rank = 0;
        for (int j = 0; j < K; ++j) {
            float vj = s_v[j]; int rj = s_r[j];
            rank += ((vj > v) || (vj == v && rj < r)) ? 1 : 0;
        }
        if (rank < TOPK) {
            g_top_iou[c][rank] = v;
            g_top_row[c][rank] = r;
        }
    }
    if (tid == 0) g_top_cnt[c] = K;
}

// -------------------------------------------------------------- k_greedy ----
// Single block, 128 threads, M iterations. Per-column best unremoved
// candidate -> packed-u64 shared atomicMax. Key = (iou_bits << 25) |
// (2^25-1 - (r*M+c)): max key == (iou desc, flattened index asc) == the
// reference's jnp.argmax over the masked matrix. flat < 2^25 (r<131072, M<=128).
__global__ void k_greedy(int N, int M) {
    __shared__ unsigned s_removed[MAXN / 32];   // 16 KB bitmap
    __shared__ unsigned char s_matched[128];
    __shared__ unsigned long long s_best;

    const int tid = threadIdx.x;
    for (int i = tid; i < MAXN / 32; i += 128) s_removed[i] = 0;
    s_matched[tid] = 0;
    if (tid == 0) s_best = 0ull;

    int ptr = 0;
    const int cnt = (tid < M) ? g_top_cnt[tid] : 0;
    __syncthreads();

    for (int it = 0; it < M; ++it) {
        unsigned long long key = 0ull;
        if (tid < M && !s_matched[tid]) {
            while (ptr < cnt) {
                int row = g_top_row[tid][ptr];
                if (s_removed[row >> 5] & (1u << (row & 31))) { ++ptr; continue; }
                unsigned vb = __float_as_uint(g_top_iou[tid][ptr]);
                unsigned flat = (unsigned)row * (unsigned)M + (unsigned)tid;
                key = ((unsigned long long)vb << 25) |
                      (unsigned long long)(0x1FFFFFFu - flat);
                break;
            }
        }
        if (key) atomicMax(&s_best, key);
        __syncthreads();

        unsigned long long b = s_best;
        __syncthreads();                        // everyone read b before reset

        if (b == 0ull) break;                   // uniform: no candidates left

        unsigned flat = 0x1FFFFFFu - (unsigned)(b & 0x1FFFFFFu);
        int bc = (int)(flat % (unsigned)M);
        int br = (int)(flat / (unsigned)M);

        if (tid == 0) {
            s_best = 0ull;
            s_removed[br >> 5] |= 1u << (br & 31);
            if (br < MAXN) g_match[br] = bc;    // bipartite overrides max-match
        }
        if (tid == bc) s_matched[tid] = 1;
        __syncthreads();
    }
}

// ----------------------------------------------------------------- k_out ----
// Layout [cls(N) | box(4N) | mask(N)] = 6N elements (validated R11):
//   cls at out[i]; box at out[N+4i..+3]; mask scalar at out[5N+i].
__global__ void k_out(const float4* __restrict__ anchors,
                      const float4* __restrict__ gt,
                      const int* __restrict__ gt_ids,
                      int N, int M, float* __restrict__ out, int out_size) {
    int i = blockIdx.x * blockDim.x + threadIdx.x;
    if (i >= N || i >= MAXN) return;

    int m = g_match[i];
    if (m >= M) m = -1;
    const bool pos = (m >= 0);

    float cls_v = 0.0f;
    float t0 = 0.0f, t1 = 0.0f, t2 = 0.0f, t3 = 0.0f, mk = 0.0f;

    if (pos) {
        cls_v = (float)gt_ids[m] + 1.0f;
        mk = 1.0f;

        float4 g = gt[m];                        // corner format
        float gw = g.z - g.x, gh = g.w - g.y;
        float gcx = g.x + 0.5f * gw, gcy = g.y + 0.5f * gh;

        float4 a = anchors[i];                   // center format
        float hw = a.z * 0.5f, hh = a.w * 0.5f;
        float ax1 = a.x - hw, ay1 = a.y - hh;
        float ax2 = a.x + hw, ay2 = a.y + hh;
        float aw = ax2 - ax1, ah = ay2 - ay1;
        float acx = ax1 + 0.5f * aw, acy = ay1 + 0.5f * ah;

        t0 = (gcx - acx) / aw / 0.1f;
        t1 = (gcy - acy) / ah / 0.1f;
        t2 = logf(gw / aw) / 0.2f;
        t3 = logf(gh / ah) / 0.2f;
    }

    if (i < out_size) out[i] = cls_v;

    int b0 = N + 4 * i;
    if (b0 + 3 < out_size) {
        *(float4*)(out + b0) = make_float4(t0, t1, t2, t3);
    } else {
        if (b0 + 0 < out_size) out[b0 + 0] = t0;
        if (b0 + 1 < out_size) out[b0 + 1] = t1;
        if (b0 + 2 < out_size) out[b0 + 2] = t2;
        if (b0 + 3 < out_size) out[b0 + 3] = t3;
    }

    int m0 = 5 * N + i;
    if (m0 < out_size) out[m0] = mk;
}

// ---------------------------------------------------------------------------
extern "C" void kernel_launch(void* const* d_in, const int* in_sizes, int n_in,
                              void* d_out, int out_size) {
    const float4* anchors = (const float4*)d_in[0];   // (N,4) center format
    const float4* gt      = (const float4*)d_in[1];   // (M,4) corner format
    const int*    gt_ids  = (const int*)d_in[2];      // (M,1) int32

    int N = in_sizes[0] / 4;
    int M = in_sizes[1] / 4;
    if (N > MAXN) N = MAXN;
    if (M > MAXM) M = MAXM;
    float* out = (float*)d_out;

    if (out_size > 6 * N) {
        int tail = out_size - 6 * N;
        int zgrid = (tail + 255) / 256;
        if (zgrid > 1184) zgrid = 1184;
        k_zero<<<zgrid, 256>>>(out, 6 * N, out_size);
    }

    k_iou<<<(N + 255) / 256, 256>>>(anchors, gt, N, M);
    k_select<<<M, 256>>>(N, M);
    k_greedy<<<1, 128>>>(N, M);
    k_out<<<(N + 255) / 256, 256>>>(anchors, gt, gt_ids, N, M, out, out_size);
}

// round 15
// speedup vs baseline: 3.3632x; 1.4358x over previous
#include <cuda_runtime.h>
#include <cstdint>

// ---------------------------------------------------------------------------
// SSDTargetGenerator for GB300.  R15 = R14 resubmit (broker timeout) with one
// contract fix: cudaFuncSetAttribute now called unconditionally (the R14
// `static bool attr_done` guard violated the "no static guards" harness rule).
// Design (vs R13's measured 256.5us):
//   k_select : batched loads (MLP=8) before ballot rounds; compacted VALUES in
//              64KB dynamic shared (radix counts = LDS); shuffle reductions.
//   k_greedy : preload all top lists into dynamic shared once (all-LDS loop).
//   k_iou/k_out unchanged (k_out measured ~6us; layout validated bit-exact).
// No global atomics. No cross-launch state. Graph-capturable.
// ---------------------------------------------------------------------------

#define MAXM    128     // max gt boxes
#define TOPK    128     // per-column survivor list (> M-1 removals)
#define MAXN    131072  // max anchors (N=120000)
#define SEGS    8       // warps per k_select block
#define SEGCAP  2048    // per-warp segment capacity (expected ~990)
#define WIN     (SEGS * SEGCAP)   // 16384-slot fixed window
#define BATCH   8       // values loaded per thread before ballot rounds

__device__ float g_iou_mat[(size_t)MAXM * MAXN];   // column-major [c*N + i]
__device__ int   g_cr[MAXM][WIN];                  // per-column compacted rows
__device__ float g_top_iou[MAXM][TOPK];
__device__ int   g_top_row[MAXM][TOPK];
__device__ int   g_top_cnt[MAXM];
__device__ int   g_match[MAXN];

// ---------------------------------------------------------------- k_zero ----
__global__ void k_zero(float* __restrict__ out, int zero_from, int out_size) {
    int stride = gridDim.x * blockDim.x;
    for (int i = zero_from + blockIdx.x * blockDim.x + threadIdx.x;
         i < out_size; i += stride)
        out[i] = 0.0f;
}

// ----------------------------------------------------------------- k_iou ----
// Per anchor: IoU vs all M gt boxes. Per-anchor argmax (first-occurrence ==
// jnp.argmax) for MaximumMatcher. Dense column-major store (coalesced): value
// if iou > 1e-12 (bipartite threshold) else 0. No atomics.
__global__ void k_iou(const float4* __restrict__ anchors,
                      const float4* __restrict__ gt,
                      int N, int M) {
    __shared__ float4 s_gt[MAXM];
    __shared__ float  s_area[MAXM];
    for (int c = threadIdx.x; c < M; c += blockDim.x) {
        float4 g = gt[c];
        s_gt[c] = g;
        s_area[c] = (g.z - g.x) * (g.w - g.y);
    }
    __syncthreads();

    const int i = blockIdx.x * blockDim.x + threadIdx.x;
    if (i >= N || i >= MAXN) return;

    float4 a = anchors[i];                     // center format (cx,cy,w,h)
    float hw = a.z * 0.5f, hh = a.w * 0.5f;
    float ax1 = a.x - hw, ay1 = a.y - hh;
    float ax2 = a.x + hw, ay2 = a.y + hh;
    float area_a = (ax2 - ax1) * (ay2 - ay1);  // replicate reference op order

    float best = 0.0f;
    int   argc = 0;

    #pragma unroll 4
    for (int c = 0; c < M; ++c) {
        float4 g = s_gt[c];
        float tlx = fmaxf(ax1, g.x), tly = fmaxf(ay1, g.y);
        float brx = fminf(ax2, g.z), bry = fminf(ay2, g.w);
        float wx = brx - tlx, wy = bry - tly;

        float val = 0.0f;
        if (wx > 0.0f && wy > 0.0f) {
            float inter = wx * wy;
            float iou = inter / (area_a + s_area[c] - inter);   // IEEE div == ref
            if (iou > best) { best = iou; argc = c; }           // first-occurrence
            if (iou > 1e-12f) val = iou;
        }
        g_iou_mat[(size_t)c * N + i] = val;
    }
    g_match[i] = (best >= 0.5f) ? argc : -1;   // MaximumMatcher
}

// -------------------------------------------------------------- k_select ----
// One block (256 thr = 8 warps) per column. Dynamic shared = 64KB value window.
// Phase 1: batched compaction — BATCH independent loads (MLP=8), then BATCH
// ballot/store rounds; values -> shared window, rows -> global g_cr.
// Phase 2: validated exact radix top-128 over the zero-padded shared window
// (T > 0, zeros can never pass), gather >T, ==T smallest rows, rank-sort
// (iou desc, row asc) == reference argmax order.
__global__ void k_select(int N, int M) {
    extern __shared__ float s_val[];            // WIN floats (64KB)
    const int c    = blockIdx.x;
    const int tid  = threadIdx.x;
    const int wid  = tid >> 5;
    const int lane = tid & 31;

    const float* __restrict__ col = g_iou_mat + (size_t)c * N;
    int* __restrict__ cr = g_cr[c];

    __shared__ int   s_cnt[SEGS];
    __shared__ int   s_wred[SEGS];
    __shared__ int   s_total;
    __shared__ int   s_pos;
    __shared__ int   s_eqn;
    __shared__ int   s_eqrows[256];
    __shared__ float s_v[TOPK];
    __shared__ int   s_r[TOPK];

    // ---- Phase 1: batched warp-segmented compaction ----
    const int wbase = wid * SEGCAP;
    int woff = 0;                               // warp-uniform running offset
    for (int base = 0; base < N; base += 256 * BATCH) {
        float v[BATCH];
        #pragma unroll
        for (int k = 0; k < BATCH; ++k) {
            int i = base + k * 256 + tid;
            v[k] = (i < N) ? col[i] : 0.0f;     // independent loads, MLP=BATCH
        }
        #pragma unroll
        for (int k = 0; k < BATCH; ++k) {
            unsigned m = __ballot_sync(0xFFFFFFFFu, v[k] > 0.0f);
            if (v[k] > 0.0f) {
                int p = woff + __popc(m & ((1u << lane) - 1u));
                if (p < SEGCAP) {
                    s_val[wbase + p] = v[k];
                    cr[wbase + p]    = base + k * 256 + tid;
                }
            }
            woff += __popc(m);
        }
    }
    int wcnt = woff < SEGCAP ? woff : SEGCAP;
    if (lane == 0) s_cnt[wid] = wcnt;
    for (int k = wcnt + lane; k < SEGCAP; k += 32) s_val[wbase + k] = 0.0f;
    __syncthreads();

    int n_total = 0;
    #pragma unroll
    for (int w = 0; w < SEGS; ++w) n_total += s_cnt[w];

    const int K = n_total < TOPK ? n_total : TOPK;
    if (K == 0) { if (tid == 0) g_top_cnt[c] = 0; return; }

    // ---- Phase 2: radix threshold T = K-th largest (bit 29 down; IoU <= 1) ----
    unsigned prefix = 0u;
    for (int b = 29; b >= 0; --b) {
        unsigned test = prefix | (1u << b);
        int local = 0;
        for (int i = tid; i < WIN; i += 256)
            local += (__float_as_uint(s_val[i]) >= test) ? 1 : 0;
        // warp shuffle reduce
        #pragma unroll
        for (int s = 16; s > 0; s >>= 1)
            local += __shfl_down_sync(0xFFFFFFFFu, local, s);
        if (lane == 0) s_wred[wid] = local;
        __syncthreads();
        if (tid == 0) {
            int tot = 0;
            #pragma unroll
            for (int w = 0; w < SEGS; ++w) tot += s_wred[w];
            s_total = tot;
        }
        __syncthreads();
        if (s_total >= K) prefix = test;
        __syncthreads();                        // protect s_wred reuse
    }
    const unsigned T = prefix;                  // T > 0 since K <= n_total

    // ---- Gather strictly-greater (unordered; rank-sorted below) ----
    if (tid == 0) s_pos = 0;
    __syncthreads();
    for (int i = tid; i < WIN; i += 256) {
        if (__float_as_uint(s_val[i]) > T) {
            int p = atomicAdd(&s_pos, 1);       // shared, < 128 total
            if (p < TOPK) {
                g_top_iou[c][p] = s_val[i];
                g_top_row[c][p] = cr[i];
            }
        }
    }
    __syncthreads();
    const int cnt_gt = s_pos < TOPK ? s_pos : TOPK;
    const int need   = K - cnt_gt;              // >= 1 by construction of T

    // ---- Entries equal to T: keep 'need' smallest rows (argmax tie order) ----
    if (tid == 0) s_eqn = 0;
    __syncthreads();
    for (int i = tid; i < WIN; i += 256) {
        if (__float_as_uint(s_val[i]) == T) {
            int p = atomicAdd(&s_eqn, 1);
            if (p < 256) s_eqrows[p] = cr[i];
        }
    }
    __syncthreads();
    const int eqn = s_eqn < 256 ? s_eqn : 256;
    if (tid < eqn) {
        int r = s_eqrows[tid];
        int rank = 0;
        for (int j = 0; j < eqn; ++j) rank += (s_eqrows[j] < r) ? 1 : 0;
        if (rank < need && (cnt_gt + rank) < TOPK) {
            g_top_iou[c][cnt_gt + rank] = __uint_as_float(T);
            g_top_row[c][cnt_gt + rank] = r;
        }
    }
    __syncthreads();

    // ---- Rank-sort K entries: iou desc, row asc on ties ----
    if (tid < K) { s_v[tid] = g_top_iou[c][tid]; s_r[tid] = g_top_row[c][tid]; }
    __syncthreads();
    if (tid < K) {
        float v = s_v[tid]; int r = s_r[tid];
        int rank = 0;
        for (int j = 0; j < K; ++j) {
            float vj = s_v[j]; int rj = s_r[j];
            rank += ((vj > v) || (vj == v && rj < r)) ? 1 : 0;
        }
        if (rank < TOPK) {
            g_top_iou[c][rank] = v;
            g_top_row[c][rank] = r;
        }
    }
    if (tid == 0) g_top_cnt[c] = K;
}

// -------------------------------------------------------------- k_greedy ----
// Single block, 128 threads, M iterations. Top lists preloaded into dynamic
// shared (one coalesced pass) so the serial loop is all-LDS. Per iteration:
// packed-u64 shared atomicMax, key = (iou_bits << 25) | (2^25-1 - (r*M+c)):
// max key == (iou desc, flat idx asc) == reference jnp.argmax. flat < 2^25.
__global__ void k_greedy(int N, int M) {
    extern __shared__ unsigned char s_dyn[];
    float* s_tv = (float*)s_dyn;                         // M*TOPK floats
    int*   s_tr = (int*)(s_dyn + (size_t)M * TOPK * 4);  // M*TOPK ints

    __shared__ unsigned s_removed[MAXN / 32];   // 16 KB bitmap
    __shared__ unsigned char s_matched[128];
    __shared__ unsigned long long s_best;

    const int tid = threadIdx.x;
    for (int i = tid; i < MAXN / 32; i += 128) s_removed[i] = 0;
    s_matched[tid] = 0;
    if (tid == 0) s_best = 0ull;

    // Preload all top lists (coalesced: g_top arrays are row-contiguous).
    for (int idx = tid; idx < M * TOPK; idx += 128) {
        int cc = idx / TOPK, kk = idx % TOPK;
        s_tv[idx] = g_top_iou[cc][kk];
        s_tr[idx] = g_top_row[cc][kk];
    }

    int ptr = 0;
    const int cnt = (tid < M) ? g_top_cnt[tid] : 0;
    __syncthreads();

    for (int it = 0; it < M; ++it) {
        unsigned long long key = 0ull;
        if (tid < M && !s_matched[tid]) {
            while (ptr < cnt) {
                int row = s_tr[tid * TOPK + ptr];
                if (s_removed[row >> 5] & (1u << (row & 31))) { ++ptr; continue; }
                unsigned vb = __float_as_uint(s_tv[tid * TOPK + ptr]);
                unsigned flat = (unsigned)row * (unsigned)M + (unsigned)tid;
                key = ((unsigned long long)vb << 25) |
                      (unsigned long long)(0x1FFFFFFu - flat);
                break;
            }
        }
        if (key) atomicMax(&s_best, key);
        __syncthreads();

        unsigned long long b = s_best;
        __syncthreads();                        // everyone read b before reset

        if (b == 0ull) break;                   // uniform: no candidates left

        unsigned flat = 0x1FFFFFFu - (unsigned)(b & 0x1FFFFFFu);
        int bc = (int)(flat % (unsigned)M);
        int br = (int)(flat / (unsigned)M);

        if (tid == 0) {
            s_best = 0ull;
            s_removed[br >> 5] |= 1u << (br & 31);
            if (br < MAXN) g_match[br] = bc;    // bipartite overrides max-match
        }
        if (tid == bc) s_matched[tid] = 1;
        __syncthreads();
    }
}

// ----------------------------------------------------------------- k_out ----
// Layout [cls(N) | box(4N) | mask(N)] = 6N (validated R11/R13, bit-exact):
// cls at out[i]; box at out[N+4i..+3]; mask scalar at out[5N+i].
__global__ void k_out(const float4* __restrict__ anchors,
                      const float4* __restrict__ gt,
                      const int* __restrict__ gt_ids,
                      int N, int M, float* __restrict__ out, int out_size) {
    int i = blockIdx.x * blockDim.x + threadIdx.x;
    if (i >= N || i >= MAXN) return;

    int m = g_match[i];
    if (m >= M) m = -1;
    const bool pos = (m >= 0);

    float cls_v = 0.0f;
    float t0 = 0.0f, t1 = 0.0f, t2 = 0.0f, t3 = 0.0f, mk = 0.0f;

    if (pos) {
        cls_v = (float)gt_ids[m] + 1.0f;
        mk = 1.0f;

        float4 g = gt[m];                        // corner format
        float gw = g.z - g.x, gh = g.w - g.y;
        float gcx = g.x + 0.5f * gw, gcy = g.y + 0.5f * gh;

        float4 a = anchors[i];                   // center format
        float hw = a.z * 0.5f, hh = a.w * 0.5f;
        float ax1 = a.x - hw, ay1 = a.y - hh;
        float ax2 = a.x + hw, ay2 = a.y + hh;
        float aw = ax2 - ax1, ah = ay2 - ay1;
        float acx = ax1 + 0.5f * aw, acy = ay1 + 0.5f * ah;

        t0 = (gcx - acx) / aw / 0.1f;
        t1 = (gcy - acy) / ah / 0.1f;
        t2 = logf(gw / aw) / 0.2f;
        t3 = logf(gh / ah) / 0.2f;
    }

    if (i < out_size) out[i] = cls_v;

    int b0 = N + 4 * i;
    if (b0 + 3 < out_size) {
        *(float4*)(out + b0) = make_float4(t0, t1, t2, t3);
    } else {
        if (b0 + 0 < out_size) out[b0 + 0] = t0;
        if (b0 + 1 < out_size) out[b0 + 1] = t1;
        if (b0 + 2 < out_size) out[b0 + 2] = t2;
        if (b0 + 3 < out_size) out[b0 + 3] = t3;
    }

    int m0 = 5 * N + i;
    if (m0 < out_size) out[m0] = mk;
}

// ---------------------------------------------------------------------------
extern "C" void kernel_launch(void* const* d_in, const int* in_sizes, int n_in,
                              void* d_out, int out_size) {
    const float4* anchors = (const float4*)d_in[0];   // (N,4) center format
    const float4* gt      = (const float4*)d_in[1];   // (M,4) corner format
    const int*    gt_ids  = (const int*)d_in[2];      // (M,1) int32

    int N = in_sizes[0] / 4;
    int M = in_sizes[1] / 4;
    if (N > MAXN) N = MAXN;
    if (M > MAXM) M = MAXM;
    float* out = (float*)d_out;

    // Host-side attribute sets: idempotent, not stream ops, capture-safe.
    // Called unconditionally every time (no static guards per harness rules).
    cudaFuncSetAttribute(k_select,
        cudaFuncAttributeMaxDynamicSharedMemorySize, WIN * 4);
    cudaFuncSetAttribute(k_greedy,
        cudaFuncAttributeMaxDynamicSharedMemorySize, MAXM * TOPK * 8);

    if (out_size > 6 * N) {
        int tail = out_size - 6 * N;
        int zgrid = (tail + 255) / 256;
        if (zgrid > 1184) zgrid = 1184;
        k_zero<<<zgrid, 256>>>(out, 6 * N, out_size);
    }

    k_iou<<<(N + 255) / 256, 256>>>(anchors, gt, N, M);
    k_select<<<M, 256, WIN * 4>>>(N, M);
    k_greedy<<<1, 128, (size_t)M * TOPK * 8>>>(N, M);
    k_out<<<(N + 255) / 256, 256>>>(anchors, gt, gt_ids, N, M, out, out_size);
}